// round 2
// baseline (speedup 1.0000x reference)
#include <cuda_runtime.h>
#include <cuda_bf16.h>

#define V_NODES 50000
#define D_DIM   128

// Scratch: node message accumulator [V, D] (25.6 MB). 16B-aligned for float4 / red.v4.
__device__ __align__(16) float g_node_msgs[V_NODES * D_DIM];
// Index dtype flag: 1 = int64 buffers, 0 = int32 buffers (JAX x64-disabled downcast)
__device__ int g_idx64;

typedef unsigned long long ull;

__device__ __forceinline__ ull pack_dup(float x) {
    ull r; asm("mov.b64 %0, {%1, %1};" : "=l"(r) : "f"(x)); return r;
}
__device__ __forceinline__ ull pack2(float x, float y) {
    ull r; asm("mov.b64 %0, {%1, %2};" : "=l"(r) : "f"(x), "f"(y)); return r;
}
__device__ __forceinline__ void unpack2(ull v, float& x, float& y) {
    asm("mov.b64 {%0, %1}, %2;" : "=f"(x), "=f"(y) : "l"(v));
}
// Packed fp32x2 FMA (Blackwell FFMA2 — only reachable via PTX, 2x fp32 throughput)
__device__ __forceinline__ void ffma2(ull& d, ull a, ull b) {
    asm("fma.rn.f32x2 %0, %1, %2, %0;" : "+l"(d) : "l"(a), "l"(b));
}

__device__ __forceinline__ long long load_idx(const void* p, long long i, bool is64) {
    if (is64) return ((const long long*)p)[i];
    return (long long)((const int*)p)[i];
}

// ---------------------------------------------------------------------------
// K-1: detect index dtype. edge_index has 2E entries, all in [0, V).
// Interpreted as int64: valid int64 data -> all sampled values in range.
// int32 data -> a sampled "int64" is lo + hi*2^32 with random hi -> out of range
// with overwhelming probability across 4096 samples.
// ---------------------------------------------------------------------------
__global__ void detect_idx_kernel(const void* edge_index, int n64) {
    __shared__ int bad;
    if (threadIdx.x == 0) bad = 0;
    __syncthreads();
    const long long* p = (const long long*)edge_index;
    for (int i = threadIdx.x; i < n64; i += blockDim.x) {
        long long v = p[i];
        if (v < 0 || v >= V_NODES) { bad = 1; break; }
    }
    __syncthreads();
    if (threadIdx.x == 0) g_idx64 = bad ? 0 : 1;
}

// ---------------------------------------------------------------------------
// K0: zero the node accumulator (graph replays require re-zeroing every launch)
// ---------------------------------------------------------------------------
__global__ void zero_nodes_kernel() {
    int i = blockIdx.x * blockDim.x + threadIdx.x;
    const int n4 = V_NODES * D_DIM / 4;
    if (i < n4) reinterpret_cast<float4*>(g_node_msgs)[i] = make_float4(0.f, 0.f, 0.f, 0.f);
}

// ---------------------------------------------------------------------------
// K1: scatter-add relu(edge_feats[e]) onto node_msgs[dest[e]]
// One warp per edge; each lane handles 4 floats; vectorized red.global.add.v4
// ---------------------------------------------------------------------------
__global__ void __launch_bounds__(256) scatter_relu_kernel(
    const float* __restrict__ edge_feats,
    const void* __restrict__ edge_index,   // dest = edge_index[1, :] = entries [E, 2E)
    int E)
{
    const bool is64 = (g_idx64 != 0);
    int warp = (blockIdx.x * blockDim.x + threadIdx.x) >> 5;
    int lane = threadIdx.x & 31;
    if (warp >= E) return;
    long long d = load_idx(edge_index, (long long)E + warp, is64);
    float4 v = reinterpret_cast<const float4*>(edge_feats + (long long)warp * D_DIM)[lane];
    v.x = fmaxf(v.x, 0.f);
    v.y = fmaxf(v.y, 0.f);
    v.z = fmaxf(v.z, 0.f);
    v.w = fmaxf(v.w, 0.f);
    float* addr = g_node_msgs + d * D_DIM + lane * 4;
    asm volatile("red.global.add.v4.f32 [%0], {%1, %2, %3, %4};"
                 :: "l"(addr), "f"(v.x), "f"(v.y), "f"(v.z), "f"(v.w) : "memory");
}

// ---------------------------------------------------------------------------
// K2: fused gather + GEMV + bias
//   x = node_msgs[src[e]] - relu(edge_feats[rev[e]])
//   out[e] = x @ W^T + b
// W^T staged in dynamic smem as Ws[k][j] (warp reads over j are conflict-free
// LDS.128). Warp per edge; thread t computes out[4t..4t+3] as two f32x2 accs.
// ---------------------------------------------------------------------------
__global__ void __launch_bounds__(256) fused_gemv_kernel(
    const float* __restrict__ edge_feats,
    const float* __restrict__ W,
    const float* __restrict__ bias,
    const void* __restrict__ edge_index,   // src = entries [0, E)
    const void* __restrict__ rev,
    float* __restrict__ out,
    int E)
{
    extern __shared__ float Wsh[];            // [128*128] = 64 KB, Ws[k*128 + j] = W[j][k]
    __shared__ float xs[8][D_DIM];            // per-warp x staging (4 KB)

    const bool is64 = (g_idx64 != 0);
    int tid = threadIdx.x;
    // Load W transposed into shared (once per block)
    for (int idx = tid; idx < D_DIM * D_DIM; idx += 256) {
        int j = idx >> 7;
        int k = idx & 127;
        Wsh[k * D_DIM + j] = W[idx];
    }
    __syncthreads();

    int warp = tid >> 5;
    int lane = tid & 31;

    // Bias held in registers (constant per thread across edges)
    float4 b4 = reinterpret_cast<const float4*>(bias)[lane];
    const ull bias0 = pack2(b4.x, b4.y);
    const ull bias1 = pack2(b4.z, b4.w);

    float* xsw = xs[warp];
    const ulonglong2* Wp = reinterpret_cast<const ulonglong2*>(Wsh);

    int gw = blockIdx.x * 8 + warp;
    int nwarps = gridDim.x * 8;

    for (int e = gw; e < E; e += nwarps) {
        long long s = load_idx(edge_index, e, is64);
        long long r = load_idx(rev, e, is64);
        float4 nm = reinterpret_cast<const float4*>(g_node_msgs + s * D_DIM)[lane];
        float4 ef = reinterpret_cast<const float4*>(edge_feats + r * D_DIM)[lane];
        float4 xv;
        xv.x = nm.x - fmaxf(ef.x, 0.f);
        xv.y = nm.y - fmaxf(ef.y, 0.f);
        xv.z = nm.z - fmaxf(ef.z, 0.f);
        xv.w = nm.w - fmaxf(ef.w, 0.f);

        __syncwarp();                                   // prior iteration's readers done
        reinterpret_cast<float4*>(xsw)[lane] = xv;
        __syncwarp();                                   // x visible to all lanes

        ull acc0 = bias0;
        ull acc1 = bias1;

        #pragma unroll
        for (int k = 0; k < D_DIM; k += 4) {
            float4 xk = reinterpret_cast<const float4*>(xsw)[k >> 2];  // broadcast LDS.128
            ull x0 = pack_dup(xk.x);
            ull x1 = pack_dup(xk.y);
            ull x2 = pack_dup(xk.z);
            ull x3 = pack_dup(xk.w);
            ulonglong2 w0 = Wp[(k + 0) * 32 + lane];    // LDS.128, conflict-free
            ffma2(acc0, x0, w0.x); ffma2(acc1, x0, w0.y);
            ulonglong2 w1 = Wp[(k + 1) * 32 + lane];
            ffma2(acc0, x1, w1.x); ffma2(acc1, x1, w1.y);
            ulonglong2 w2 = Wp[(k + 2) * 32 + lane];
            ffma2(acc0, x2, w2.x); ffma2(acc1, x2, w2.y);
            ulonglong2 w3 = Wp[(k + 3) * 32 + lane];
            ffma2(acc0, x3, w3.x); ffma2(acc1, x3, w3.y);
        }

        float4 o;
        unpack2(acc0, o.x, o.y);
        unpack2(acc1, o.z, o.w);
        reinterpret_cast<float4*>(out + (long long)e * D_DIM)[lane] = o;
    }
}

// ---------------------------------------------------------------------------
// launch
// ---------------------------------------------------------------------------
extern "C" void kernel_launch(void* const* d_in, const int* in_sizes, int n_in,
                              void* d_out, int out_size)
{
    const float* edge_feats = (const float*)d_in[0];
    // d_in[1] = node_feats [V,1]: values unused by the math (only V matters).
    const float* W          = (const float*)d_in[2];
    const float* b          = (const float*)d_in[3];
    const void*  edge_index = d_in[4];
    const void*  rev_index  = d_in[5];
    float*       out        = (float*)d_out;

    const int E = in_sizes[0] / D_DIM;

    // K-1: detect whether index buffers are int64 or int32
    {
        int n64 = 2 * E < 4096 ? 2 * E : 4096;   // sample entries as int64
        detect_idx_kernel<<<1, 256>>>(edge_index, n64);
    }

    // K0: zero accumulator
    {
        int n4 = V_NODES * D_DIM / 4;
        zero_nodes_kernel<<<(n4 + 255) / 256, 256>>>();
    }

    // K1: scatter relu messages (warp per edge)
    {
        int threads = 256;
        int warps_per_block = threads / 32;
        int blocks = (E + warps_per_block - 1) / warps_per_block;
        scatter_relu_kernel<<<blocks, threads>>>(edge_feats, edge_index, E);
    }

    // K2: fused gather + GEMV
    {
        static bool attr_set = false;
        if (!attr_set) {
            cudaFuncSetAttribute(fused_gemv_kernel,
                                 cudaFuncAttributeMaxDynamicSharedMemorySize,
                                 D_DIM * D_DIM * (int)sizeof(float));
            attr_set = true;
        }
        int blocks = 456;  // 152 SMs * 3 blocks (68 KB smem each)
        fused_gemv_kernel<<<blocks, 256, D_DIM * D_DIM * sizeof(float)>>>(
            edge_feats, W, b, edge_index, rev_index, out, E);
    }
}

// round 4
// speedup vs baseline: 2.6938x; 2.6938x over previous
#include <cuda_runtime.h>
#include <cuda_bf16.h>

#define V_NODES 50000
#define D_DIM   128
#define TILE_E  128
#define PITCH_X 132            // 128 + 4 pad, keeps float4 alignment, de-conflicts banks

// Scratch (static device globals — no allocs)
__device__ __align__(16) float g_node_msgs[V_NODES * D_DIM];  // 25.6 MB
__device__ __align__(16) float g_WT[D_DIM * D_DIM];           // W transposed: WT[k][j] = W[j][k]
__device__ int g_idx64;                                        // 1 = int64 indices, 0 = int32

typedef unsigned long long ull;

__device__ __forceinline__ ull pack_dup(float x) {
    ull r; asm("mov.b64 %0, {%1, %1};" : "=l"(r) : "f"(x)); return r;
}
__device__ __forceinline__ ull pack2(float x, float y) {
    ull r; asm("mov.b64 %0, {%1, %2};" : "=l"(r) : "f"(x), "f"(y)); return r;
}
__device__ __forceinline__ void unpack2(ull v, float& x, float& y) {
    asm("mov.b64 {%0, %1}, %2;" : "=f"(x), "=f"(y) : "l"(v));
}
// Packed fp32x2 FMA (Blackwell FFMA2 — only reachable via PTX, 2x fp32 throughput)
__device__ __forceinline__ void ffma2(ull& d, ull a, ull b) {
    asm("fma.rn.f32x2 %0, %1, %2, %0;" : "+l"(d) : "l"(a), "l"(b));
}

__device__ __forceinline__ long long load_idx(const void* p, long long i, bool is64) {
    if (is64) return ((const long long*)p)[i];
    return (long long)((const int*)p)[i];
}

// ---------------------------------------------------------------------------
// detect index dtype (int64 vs JAX-downcast int32)
// ---------------------------------------------------------------------------
__global__ void detect_idx_kernel(const void* edge_index, int n64) {
    __shared__ int bad;
    if (threadIdx.x == 0) bad = 0;
    __syncthreads();
    const long long* p = (const long long*)edge_index;
    for (int i = threadIdx.x; i < n64; i += blockDim.x) {
        long long v = p[i];
        if (v < 0 || v >= V_NODES) { bad = 1; break; }
    }
    __syncthreads();
    if (threadIdx.x == 0) g_idx64 = bad ? 0 : 1;
}

// ---------------------------------------------------------------------------
// zero node accumulator
// ---------------------------------------------------------------------------
__global__ void zero_nodes_kernel() {
    int i = blockIdx.x * blockDim.x + threadIdx.x;
    const int n4 = V_NODES * D_DIM / 4;
    if (i < n4) reinterpret_cast<float4*>(g_node_msgs)[i] = make_float4(0.f, 0.f, 0.f, 0.f);
}

// ---------------------------------------------------------------------------
// transpose W once into gmem (so compute blocks get coalesced, conflict-free fills)
// ---------------------------------------------------------------------------
__global__ void transpose_w_kernel(const float* __restrict__ W) {
    int idx = blockIdx.x * blockDim.x + threadIdx.x;   // over 16384 elements
    if (idx < D_DIM * D_DIM) {
        int k = idx >> 7;           // output row
        int j = idx & 127;          // output col
        g_WT[idx] = W[j * D_DIM + k];
    }
}

// ---------------------------------------------------------------------------
// scatter-add relu(edge_feats[e]) onto node_msgs[dest[e]]  (warp/edge, red.v4)
// ---------------------------------------------------------------------------
__global__ void __launch_bounds__(256) scatter_relu_kernel(
    const float* __restrict__ edge_feats,
    const void* __restrict__ edge_index,   // dest = entries [E, 2E)
    int E)
{
    const bool is64 = (g_idx64 != 0);
    int warp = (blockIdx.x * blockDim.x + threadIdx.x) >> 5;
    int lane = threadIdx.x & 31;
    if (warp >= E) return;
    long long d = load_idx(edge_index, (long long)E + warp, is64);
    float4 v = reinterpret_cast<const float4*>(edge_feats + (long long)warp * D_DIM)[lane];
    v.x = fmaxf(v.x, 0.f);
    v.y = fmaxf(v.y, 0.f);
    v.z = fmaxf(v.z, 0.f);
    v.w = fmaxf(v.w, 0.f);
    float* addr = g_node_msgs + d * D_DIM + lane * 4;
    asm volatile("red.global.add.v4.f32 [%0], {%1, %2, %3, %4};"
                 :: "l"(addr), "f"(v.x), "f"(v.y), "f"(v.z), "f"(v.w) : "memory");
}

// ---------------------------------------------------------------------------
// Tiled fused kernel: per block, one tile of 128 edges.
//   gather X[r][k] = node_msgs[src][k] - relu(edge_feats[rev][k]) into smem
//   C[128][128] = X @ WT  (8x8 register blocking, FFMA2), + bias, store.
// ---------------------------------------------------------------------------
__global__ void __launch_bounds__(256, 1) tile_gemm_kernel(
    const float* __restrict__ edge_feats,
    const float* __restrict__ bias,
    const void* __restrict__ edge_index,   // src = entries [0, E)
    const void* __restrict__ rev,
    float* __restrict__ out,
    int E)
{
    extern __shared__ float smem[];
    float* Wsh = smem;                       // [128][128]  = 64 KB  (Ws[k][j])
    float* Xs  = smem + D_DIM * D_DIM;       // [128][PITCH_X] ≈ 66 KB
    __shared__ int src_s[TILE_E];
    __shared__ int rev_s[TILE_E];

    const bool is64 = (g_idx64 != 0);
    const int tid  = threadIdx.x;
    const int warp = tid >> 5;
    const int lane = tid & 31;
    const long long tile_base = (long long)blockIdx.x * TILE_E;

    // --- fill Ws from pre-transposed gmem (coalesced, conflict-free) ---
    {
        const float4* wt4 = reinterpret_cast<const float4*>(g_WT);
        float4* ws4 = reinterpret_cast<float4*>(Wsh);
        #pragma unroll
        for (int i = 0; i < 16; i++)           // 4096 float4 / 256 threads
            ws4[tid + i * 256] = wt4[tid + i * 256];
    }

    // --- stage indices ---
    if (tid < TILE_E) {
        long long e = tile_base + tid;
        int s = 0, r = 0;
        if (e < E) {
            s = (int)load_idx(edge_index, e, is64);
            r = (int)load_idx(rev, e, is64);
        }
        src_s[tid] = s;
        rev_s[tid] = r;
    }
    __syncthreads();

    // --- gather X tile: warp w handles rows w*16 .. w*16+15 ---
    {
        int row0 = warp * 16;
        #pragma unroll 4
        for (int it = 0; it < 16; it++) {
            int row = row0 + it;
            if (tile_base + row < E) {
                long long s = src_s[row];
                long long r = rev_s[row];
                float4 nm = reinterpret_cast<const float4*>(g_node_msgs + s * D_DIM)[lane];
                float4 ef = reinterpret_cast<const float4*>(edge_feats + r * D_DIM)[lane];
                float4 xv;
                xv.x = nm.x - fmaxf(ef.x, 0.f);
                xv.y = nm.y - fmaxf(ef.y, 0.f);
                xv.z = nm.z - fmaxf(ef.z, 0.f);
                xv.w = nm.w - fmaxf(ef.w, 0.f);
                *reinterpret_cast<float4*>(Xs + row * PITCH_X + lane * 4) = xv;
            }
        }
    }
    __syncthreads();

    // --- compute: thread (ty, tx) computes rows ty*8..+8, cols tx*8..+8 ---
    const int tx = tid & 15;
    const int ty = tid >> 4;

    ull acc[8][4];
    {
        float4 b0 = reinterpret_cast<const float4*>(bias)[tx * 2];
        float4 b1 = reinterpret_cast<const float4*>(bias)[tx * 2 + 1];
        ull a0 = pack2(b0.x, b0.y), a1 = pack2(b0.z, b0.w);
        ull a2 = pack2(b1.x, b1.y), a3 = pack2(b1.z, b1.w);
        #pragma unroll
        for (int i = 0; i < 8; i++) {
            acc[i][0] = a0; acc[i][1] = a1; acc[i][2] = a2; acc[i][3] = a3;
        }
    }

    const float* Xbase = Xs + ty * 8 * PITCH_X;
    // W row = 128 floats = 512 B = 32 ulonglong2.  (R3 bug: pitch was 16.)
    const ulonglong2* Wp = reinterpret_cast<const ulonglong2*>(Wsh);

    #pragma unroll 2
    for (int k0 = 0; k0 < D_DIM; k0 += 4) {
        float4 xr[8];
        #pragma unroll
        for (int i = 0; i < 8; i++)
            xr[i] = *reinterpret_cast<const float4*>(Xbase + i * PITCH_X + k0);

        #pragma unroll
        for (int kk = 0; kk < 4; kk++) {
            ulonglong2 wl = Wp[(k0 + kk) * 32 + tx * 2];
            ulonglong2 wh = Wp[(k0 + kk) * 32 + tx * 2 + 1];
            #pragma unroll
            for (int i = 0; i < 8; i++) {
                float xv = (kk == 0) ? xr[i].x : (kk == 1) ? xr[i].y
                         : (kk == 2) ? xr[i].z : xr[i].w;
                ull xd = pack_dup(xv);
                ffma2(acc[i][0], xd, wl.x);
                ffma2(acc[i][1], xd, wl.y);
                ffma2(acc[i][2], xd, wh.x);
                ffma2(acc[i][3], xd, wh.y);
            }
        }
    }

    // --- store ---
    #pragma unroll
    for (int i = 0; i < 8; i++) {
        long long e = tile_base + ty * 8 + i;
        if (e < E) {
            float4 o0, o1;
            unpack2(acc[i][0], o0.x, o0.y);
            unpack2(acc[i][1], o0.z, o0.w);
            unpack2(acc[i][2], o1.x, o1.y);
            unpack2(acc[i][3], o1.z, o1.w);
            float4* op = reinterpret_cast<float4*>(out + e * D_DIM);
            op[tx * 2]     = o0;
            op[tx * 2 + 1] = o1;
        }
    }
}

// ---------------------------------------------------------------------------
// launch
// ---------------------------------------------------------------------------
extern "C" void kernel_launch(void* const* d_in, const int* in_sizes, int n_in,
                              void* d_out, int out_size)
{
    const float* edge_feats = (const float*)d_in[0];
    // d_in[1] = node_feats [V,1]: values unused by the math (only V matters).
    const float* W          = (const float*)d_in[2];
    const float* b          = (const float*)d_in[3];
    const void*  edge_index = d_in[4];
    const void*  rev_index  = d_in[5];
    float*       out        = (float*)d_out;

    const int E = in_sizes[0] / D_DIM;

    // detect index dtype
    {
        int n64 = 2 * E < 4096 ? 2 * E : 4096;
        detect_idx_kernel<<<1, 256>>>(edge_index, n64);
    }

    // zero accumulator
    {
        int n4 = V_NODES * D_DIM / 4;
        zero_nodes_kernel<<<(n4 + 255) / 256, 256>>>();
    }

    // transpose W (tiny)
    transpose_w_kernel<<<(D_DIM * D_DIM + 255) / 256, 256>>>(W);

    // scatter relu messages
    {
        int blocks = (E + 7) / 8;   // 8 warps per 256-thread block
        scatter_relu_kernel<<<blocks, 256>>>(edge_feats, edge_index, E);
    }

    // tiled fused gather + GEMM
    {
        const int smem_bytes = (D_DIM * D_DIM + TILE_E * PITCH_X) * (int)sizeof(float);
        static bool attr_set = false;
        if (!attr_set) {
            cudaFuncSetAttribute(tile_gemm_kernel,
                                 cudaFuncAttributeMaxDynamicSharedMemorySize, smem_bytes);
            attr_set = true;
        }
        int blocks = (E + TILE_E - 1) / TILE_E;
        tile_gemm_kernel<<<blocks, 256, smem_bytes>>>(
            edge_feats, b, edge_index, rev_index, out, E);
    }
}